// round 2
// baseline (speedup 1.0000x reference)
#include <cuda_runtime.h>

#define HH 384
#define WW 384
#define BB 8
#define CC 4
#define NPIX (HH*WW)        // 147456
#define NINST (BB*CC)       // 32
#define BIGF 1e8f
#define NBLK3 4608          // (BB*NPIX)/256 exactly

// Scratch: d1[pol][b][c][h][w]  (row-pass squared horizontal distances)
__device__ float g_d1[2u * NINST * NPIX];   // ~37.75 MB
__device__ float g_part[NBLK3];

// ---------------------------------------------------------------------------
// nearest set-bit squared distance in a 384-bit row (12 words), optionally on
// the complement. Returns BIGF if no set bit (matches reference:
// min_y BIG+(x-y)^2 = BIG, attained at y=x).
__device__ __forceinline__ float nearest_sq(const unsigned* __restrict__ words, int x, bool inv) {
    int w0 = x >> 5, b0 = x & 31;
    unsigned wv = words[w0]; if (inv) wv = ~wv;

    int dl = 1 << 29;
    unsigned curl = wv & (0xFFFFFFFFu >> (31 - b0));   // bits 0..b0
    int wl = w0;
    while (curl == 0 && wl > 0) {
        --wl;
        unsigned t = words[wl]; if (inv) t = ~t;
        curl = t;
    }
    if (curl) dl = x - (wl * 32 + (31 - __clz(curl)));

    int dr = 1 << 29;
    unsigned curr = wv & (0xFFFFFFFFu << b0);          // bits b0..31
    int wr = w0;
    while (curr == 0 && wr < 11) {
        ++wr;
        unsigned t = words[wr]; if (inv) t = ~t;
        curr = t;
    }
    if (curr) dr = (wr * 32 + (__ffs(curr) - 1)) - x;

    int d = min(dl, dr);
    if (d >= (1 << 28)) return BIGF;
    float fd = (float)d;
    return fd * fd;
}

// Row pass: one block per (b,h) row; 384 threads. Ballot-based bitmasks per
// class, exact nearest-bit distances, coalesced d1 writes.
__global__ void k_rowpass(const int* __restrict__ targets) {
    __shared__ unsigned mEq[CC][12];

    int b = blockIdx.x / HH;
    int h = blockIdx.x % HH;
    int x = threadIdx.x;          // 0..383
    int warp = x >> 5, lane = x & 31;

    int t = targets[(b * HH + h) * WW + x];

#pragma unroll
    for (int c = 0; c < CC; ++c) {
        unsigned m = __ballot_sync(0xFFFFFFFFu, t == c);
        if (lane == 0) mEq[c][warp] = m;
    }
    __syncthreads();

#pragma unroll
    for (int c = 0; c < CC; ++c) {
        float deq = nearest_sq(mEq[c], x, false);
        float dne = nearest_sq(mEq[c], x, true);
        int inst = b * CC + c;
        g_d1[((unsigned)inst * NPIX) + h * WW + x] = deq;
        g_d1[((unsigned)(NINST + inst) * NPIX) + h * WW + x] = dne;
    }
}

// ---------------------------------------------------------------------------
// Fused col pass for all 8 surfaces (4 classes x 2 polarities) in ONE dh loop:
// exact vertical min-plus with per-surface early exit (once q >= best[s], all
// remaining candidates for s are >= q >= best[s]); loop exits when every
// surface is settled. Up to 16 independent predicated loads in flight per
// iteration. Then phi + softmax + weighted partial sum (deterministic order).
__global__ void __launch_bounds__(256) k_loss(const float* __restrict__ logits) {
    int pid = blockIdx.x * 256 + threadIdx.x;     // 0 .. BB*NPIX-1 (exact)
    int b = pid / NPIX;
    int r = pid - b * NPIX;
    int h = r / WW;

    const float* p[8];
#pragma unroll
    for (int c = 0; c < CC; ++c) {
        int inst = b * CC + c;
        p[2 * c]     = g_d1 + (unsigned)inst * NPIX;
        p[2 * c + 1] = g_d1 + (unsigned)(NINST + inst) * NPIX;
    }

    float best[8];
#pragma unroll
    for (int s = 0; s < 8; ++s) best[s] = __ldg(p[s] + r);

    float q = 1.0f, stp = 3.0f;      // q = dh^2; next increment 2*dh+1
    int offm = r - WW, offp = r + WW;
    int hm = h - 1, hp = h + 1;
#pragma unroll 1
    for (int dh = 1; dh < HH; ++dh) {
        float mx = best[0];
#pragma unroll
        for (int s = 1; s < 8; ++s) mx = fmaxf(mx, best[s]);
        if (q >= mx) break;
        bool vm = (hm >= 0), vp = (hp < HH);
#pragma unroll
        for (int s = 0; s < 8; ++s) {
            if (q < best[s]) {
                if (vm) best[s] = fminf(best[s], __ldg(p[s] + offm) + q);
                if (vp) best[s] = fminf(best[s], __ldg(p[s] + offp) + q);
            }
        }
        q += stp; stp += 2.0f;
        offm -= WW; offp += WW; --hm; ++hp;
    }

    // softmax over 4 logits
    float l0 = logits[(b * CC + 0) * NPIX + r];
    float l1 = logits[(b * CC + 1) * NPIX + r];
    float l2 = logits[(b * CC + 2) * NPIX + r];
    float l3 = logits[(b * CC + 3) * NPIX + r];
    float m = fmaxf(fmaxf(l0, l1), fmaxf(l2, l3));
    float e0 = __expf(l0 - m), e1 = __expf(l1 - m);
    float e2 = __expf(l2 - m), e3 = __expf(l3 - m);
    float inv = 1.0f / (e0 + e1 + e2 + e3);
    float pr[4] = { e0 * inv, e1 * inv, e2 * inv, e3 * inv };

    float acc = 0.0f;
#pragma unroll
    for (int c = 0; c < CC; ++c) {
        float pos2 = best[2 * c], neg2 = best[2 * c + 1];
        // Empty/full mask detection from EDT values: finite dist^2 <= 2*383^2
        // ~ 2.9e5 << 1e7; empty-mask surface stays at BIGF = 1e8 exactly.
        float phi;
        if (pos2 >= 1e7f)       phi =  sqrtf(pos2);         // mask empty -> pos
        else if (neg2 >= 1e7f)  phi = -sqrtf(neg2);         // mask full  -> -neg
        else                    phi =  sqrtf(pos2) - sqrtf(neg2) + 1.0f;
        acc += pr[c] * phi;
    }

    // block reduction (fixed shape -> deterministic)
    int lane = threadIdx.x & 31, wid = threadIdx.x >> 5;
#pragma unroll
    for (int o = 16; o; o >>= 1) acc += __shfl_down_sync(0xFFFFFFFFu, acc, o);
    __shared__ float sm[8];
    if (lane == 0) sm[wid] = acc;
    __syncthreads();
    if (threadIdx.x < 8) {
        float v = sm[threadIdx.x];
#pragma unroll
        for (int o = 4; o; o >>= 1) v += __shfl_down_sync(0x000000FFu, v, o);
        if (threadIdx.x == 0) g_part[blockIdx.x] = v;
    }
}

// ---------------------------------------------------------------------------
// Final reduce: 18 fully independent loads per thread (MLP), then add tree.
__global__ void __launch_bounds__(256) k_final(float* __restrict__ out) {
    int t = threadIdx.x;
    float a[18];
#pragma unroll
    for (int i = 0; i < 18; ++i) a[i] = g_part[t + i * 256];
    float s = 0.0f;
#pragma unroll
    for (int i = 0; i < 18; ++i) s += a[i];

    int lane = t & 31, wid = t >> 5;
#pragma unroll
    for (int o = 16; o; o >>= 1) s += __shfl_down_sync(0xFFFFFFFFu, s, o);
    __shared__ float sm[8];
    if (lane == 0) sm[wid] = s;
    __syncthreads();
    if (t < 8) {
        float v = sm[t];
#pragma unroll
        for (int o = 4; o; o >>= 1) v += __shfl_down_sync(0x000000FFu, v, o);
        if (t == 0)
            out[0] = v * (1.0f / ((float)BB * CC * NPIX));
    }
}

// ---------------------------------------------------------------------------
extern "C" void kernel_launch(void* const* d_in, const int* in_sizes, int n_in,
                              void* d_out, int out_size) {
    const float* logits  = (const float*)d_in[0];
    const int*   targets = (const int*)d_in[1];
    float* out = (float*)d_out;

    k_rowpass<<<BB * HH, 384>>>(targets);
    k_loss<<<NBLK3, 256>>>(logits);
    k_final<<<1, 256>>>(out);
}

// round 3
// speedup vs baseline: 1.1598x; 1.1598x over previous
#include <cuda_runtime.h>

#define HH 384
#define WW 384
#define BB 8
#define CC 4
#define NPIX (HH*WW)        // 147456
#define NINST (BB*CC)       // 32
#define BIGF 1e8f
#define NBLK3 4608          // (BB*NPIX)/256 exactly

// Scratch: d1[pol][b][c][h][w]  (row-pass squared horizontal distances)
__device__ float g_d1[2u * NINST * NPIX];   // ~37.75 MB
__device__ float g_part[NBLK3];

// ---------------------------------------------------------------------------
// nearest set-bit squared distance in a 384-bit row (12 words), optionally on
// the complement. Returns BIGF if no set bit (matches reference:
// min_y BIG+(x-y)^2 = BIG, attained at y=x).
__device__ __forceinline__ float nearest_sq(const unsigned* __restrict__ words, int x, bool inv) {
    int w0 = x >> 5, b0 = x & 31;
    unsigned wv = words[w0]; if (inv) wv = ~wv;

    int dl = 1 << 29;
    unsigned curl = wv & (0xFFFFFFFFu >> (31 - b0));   // bits 0..b0
    int wl = w0;
    while (curl == 0 && wl > 0) {
        --wl;
        unsigned t = words[wl]; if (inv) t = ~t;
        curl = t;
    }
    if (curl) dl = x - (wl * 32 + (31 - __clz(curl)));

    int dr = 1 << 29;
    unsigned curr = wv & (0xFFFFFFFFu << b0);          // bits b0..31
    int wr = w0;
    while (curr == 0 && wr < 11) {
        ++wr;
        unsigned t = words[wr]; if (inv) t = ~t;
        curr = t;
    }
    if (curr) dr = (wr * 32 + (__ffs(curr) - 1)) - x;

    int d = min(dl, dr);
    if (d >= (1 << 28)) return BIGF;
    float fd = (float)d;
    return fd * fd;
}

// Row pass: one block per (b,h) row; 384 threads.
// Key algebraic cut: for a pixel of class c0,
//   deq(c0) = 0            (pixel itself is in the mask)
//   dne(c)  = 0 for c!=c0  (pixel itself is in that mask's complement)
// so only 3 eq-scans (c != c0) + 1 complement-scan (c0) are needed.
__global__ void k_rowpass(const int* __restrict__ targets) {
    __shared__ unsigned mEq[CC][12];

    int b = blockIdx.x / HH;
    int h = blockIdx.x % HH;
    int x = threadIdx.x;          // 0..383
    int warp = x >> 5, lane = x & 31;

    int t = targets[(b * HH + h) * WW + x];

#pragma unroll
    for (int c = 0; c < CC; ++c) {
        unsigned m = __ballot_sync(0xFFFFFFFFu, t == c);
        if (lane == 0) mEq[c][warp] = m;
    }
    __syncthreads();

    float dne_own = nearest_sq(mEq[t], x, true);   // complement scan, own class
    unsigned base = (unsigned)(b * CC) * NPIX + h * WW + x;

#pragma unroll
    for (int c = 0; c < CC; ++c) {
        bool own = (c == t);
        float deq = own ? 0.0f : nearest_sq(mEq[c], x, false);
        float dne = own ? dne_own : 0.0f;
        g_d1[base + (unsigned)c * NPIX] = deq;
        g_d1[(unsigned)NINST * NPIX + base + (unsigned)c * NPIX] = dne;
    }
}

// ---------------------------------------------------------------------------
// Exact vertical min-plus with early exit: once q >= best, all remaining
// candidates are >= q >= best. All finite arithmetic exact in fp32.
__device__ __forceinline__ float ringmin(const float* __restrict__ p, int h, int w) {
    float best = __ldg(p + h * WW + w);
    float q = 1.0f, step = 3.0f;   // q = dh^2, next increment 2*dh+1
#pragma unroll 1
    for (int dh = 1; dh < HH; ++dh) {
        if (q >= best) break;
        int hm = h - dh, hp = h + dh;
        if (hm >= 0) best = fminf(best, __ldg(p + hm * WW + w) + q);
        if (hp < HH) best = fminf(best, __ldg(p + hp * WW + w) + q);
        q += step; step += 2.0f;
    }
    return best;
}

// Fused: col pass (both polarities, 4 classes) + phi + softmax + weighted sum,
// block partial to fixed slot (deterministic).
__global__ void __launch_bounds__(256) k_loss(const float* __restrict__ logits) {
    int pid = blockIdx.x * 256 + threadIdx.x;     // 0 .. BB*NPIX-1 (exact)
    int b = pid / NPIX;
    int r = pid - b * NPIX;
    int h = r / WW;
    int w = r - h * WW;

    float l0 = logits[(b * CC + 0) * NPIX + r];
    float l1 = logits[(b * CC + 1) * NPIX + r];
    float l2 = logits[(b * CC + 2) * NPIX + r];
    float l3 = logits[(b * CC + 3) * NPIX + r];
    float m = fmaxf(fmaxf(l0, l1), fmaxf(l2, l3));
    float e0 = __expf(l0 - m), e1 = __expf(l1 - m);
    float e2 = __expf(l2 - m), e3 = __expf(l3 - m);
    float inv = 1.0f / (e0 + e1 + e2 + e3);
    float pr[4] = { e0 * inv, e1 * inv, e2 * inv, e3 * inv };

    float acc = 0.0f;
#pragma unroll 1
    for (int c = 0; c < CC; ++c) {
        int inst = b * CC + c;
        const float* pp = g_d1 + (unsigned)inst * NPIX;
        const float* pn = g_d1 + (unsigned)(NINST + inst) * NPIX;
        float pos2 = ringmin(pp, h, w);
        float neg2 = ringmin(pn, h, w);
        // Empty/full mask detection from EDT values: finite dist^2 <= 2*383^2
        // ~ 2.9e5 << 1e7; empty-mask surface stays at BIGF = 1e8 exactly.
        float phi;
        if (pos2 >= 1e7f)       phi =  sqrtf(pos2);         // mask empty -> pos
        else if (neg2 >= 1e7f)  phi = -sqrtf(neg2);         // mask full  -> -neg
        else                    phi =  sqrtf(pos2) - sqrtf(neg2) + 1.0f;
        acc += pr[c] * phi;
    }

    // block reduction (fixed shape -> deterministic)
    int lane = threadIdx.x & 31, wid = threadIdx.x >> 5;
#pragma unroll
    for (int o = 16; o; o >>= 1) acc += __shfl_down_sync(0xFFFFFFFFu, acc, o);
    __shared__ float sm[8];
    if (lane == 0) sm[wid] = acc;
    __syncthreads();
    if (threadIdx.x < 8) {
        float v = sm[threadIdx.x];
#pragma unroll
        for (int o = 4; o; o >>= 1) v += __shfl_down_sync(0x000000FFu, v, o);
        if (threadIdx.x == 0) g_part[blockIdx.x] = v;
    }
}

// ---------------------------------------------------------------------------
// Final reduce: 18 fully independent loads per thread (MLP), then add tree.
__global__ void __launch_bounds__(256) k_final(float* __restrict__ out) {
    int t = threadIdx.x;
    float a[18];
#pragma unroll
    for (int i = 0; i < 18; ++i) a[i] = g_part[t + i * 256];
    float s = 0.0f;
#pragma unroll
    for (int i = 0; i < 18; ++i) s += a[i];

    int lane = t & 31, wid = t >> 5;
#pragma unroll
    for (int o = 16; o; o >>= 1) s += __shfl_down_sync(0xFFFFFFFFu, s, o);
    __shared__ float sm[8];
    if (lane == 0) sm[wid] = s;
    __syncthreads();
    if (t < 8) {
        float v = sm[t];
#pragma unroll
        for (int o = 4; o; o >>= 1) v += __shfl_down_sync(0x000000FFu, v, o);
        if (t == 0)
            out[0] = v * (1.0f / ((float)BB * CC * NPIX));
    }
}

// ---------------------------------------------------------------------------
extern "C" void kernel_launch(void* const* d_in, const int* in_sizes, int n_in,
                              void* d_out, int out_size) {
    const float* logits  = (const float*)d_in[0];
    const int*   targets = (const int*)d_in[1];
    float* out = (float*)d_out;

    k_rowpass<<<BB * HH, 384>>>(targets);
    k_loss<<<NBLK3, 256>>>(logits);
    k_final<<<1, 256>>>(out);
}

// round 6
// speedup vs baseline: 1.9054x; 1.6429x over previous
#include <cuda_runtime.h>

#define HH 384
#define WW 384
#define BB 8
#define CC 4
#define NPIX (HH*WW)        // 147456
#define NINST (BB*CC)       // 32
#define BIGF 1e8f
#define NBLK3 4608          // (BB*NPIX)/256 exactly
#define DINF (1 << 28)

// Signed row-pass field: w[b][c][h][x] = (t==c) ? -dne^2 (or -BIG) : +deq^2 (or +BIG)
// Decode: d1_eq = max(w,0), d1_ne = max(-w,0). Exact (|w| >= 1 or |w| = 1e8).
__device__ float g_w[(unsigned)NINST * NPIX];   // ~18.9 MB
__device__ float g_part[NBLK3];

// ---------------------------------------------------------------------------
// Rare-path exact full-row scan (12 words), optional complement.
// Returns integer distance to nearest set bit, or DINF if none.
__device__ int full_scan(const unsigned* __restrict__ words, int x, bool inv) {
    int w0 = x >> 5, b0 = x & 31;
    unsigned wv = words[w0]; if (inv) wv = ~wv;

    int dl = DINF;
    unsigned curl = wv & (0xFFFFFFFFu >> (31 - b0));
    int wl = w0;
    while (curl == 0 && wl > 0) {
        --wl; unsigned t = words[wl]; if (inv) t = ~t; curl = t;
    }
    if (curl) dl = x - (wl * 32 + (31 - __clz(curl)));

    int dr = DINF;
    unsigned curr = wv & (0xFFFFFFFFu << b0);
    int wr = w0;
    while (curr == 0 && wr < 11) {
        ++wr; unsigned t = words[wr]; if (inv) t = ~t; curr = t;
    }
    if (curr) dr = (wr * 32 + (__ffs(curr) - 1)) - x;

    return min(dl, dr);
}

// 64-bit window of row bits [x-32, x+31], from padded word array (Wp[0]=Wp[13]=0,
// real words at Wp[1..12]). Branch-free.
__device__ __forceinline__ unsigned long long build_win(const unsigned* __restrict__ Wp, int x) {
    int j = x >> 5, sh = x & 31;
    unsigned long long A = (unsigned long long)Wp[j] | ((unsigned long long)Wp[j + 1] << 32);
    unsigned long long B = (unsigned long long)Wp[j + 2];
    return (A >> sh) | ((B << (63 - sh)) << 1);   // sh==0 -> high part 0
}

// Validity mask: window bit i is a real row position iff 0 <= x-32+i < 384.
__device__ __forceinline__ unsigned long long edge_mask(int x) {
    unsigned long long vlo = (x >= 32)  ? ~0ull : (~0ull << (32 - x));
    unsigned long long vhi = (x <= 352) ? ~0ull : (~0ull >> (x - 352));
    return vlo & vhi;
}

// Min |i-32| over set bits of win (bit 32 = self); DINF if win==0.
__device__ __forceinline__ int win_dist(unsigned long long win) {
    unsigned long long lowp  = win & 0x1FFFFFFFFULL;  // bits 0..32
    unsigned long long highp = win >> 32;             // bits 32..63
    int dl = lowp  ? (32 - (63 - __clzll(lowp))) : DINF;
    int dr = highp ? (__ffsll(highp) - 1)        : DINF;
    return min(dl, dr);
}

// ---------------------------------------------------------------------------
// Row pass: one block per (b,h) row; 384 threads. Branch-free window scans
// (fallback full scan ~never taken for iid data, kept for exactness).
// Only 3 eq-scans (c != t) + 1 complement-scan (c == t) needed per pixel.
__global__ void k_rowpass(const int* __restrict__ targets) {
    __shared__ unsigned Wp[CC][14];   // padded: [0] and [13] are zero

    int b = blockIdx.x / HH;
    int h = blockIdx.x % HH;
    int x = threadIdx.x;          // 0..383
    int warp = x >> 5, lane = x & 31;

    int t = targets[(b * HH + h) * WW + x];

#pragma unroll
    for (int c = 0; c < CC; ++c) {
        unsigned m = __ballot_sync(0xFFFFFFFFu, t == c);
        if (lane == 0) Wp[c][warp + 1] = m;
    }
    if (x < CC) { Wp[x][0] = 0; Wp[x][13] = 0; }
    __syncthreads();

    // own-class complement distance
    unsigned long long wn = (~build_win(Wp[t], x)) & edge_mask(x);
    int dn = win_dist(wn);
    if (dn >= DINF) dn = full_scan(&Wp[t][1], x, true);
    float w_own = (dn >= DINF) ? -BIGF : -((float)dn * (float)dn);

    unsigned base = (unsigned)(b * CC) * NPIX + h * WW + x;

#pragma unroll
    for (int c = 0; c < CC; ++c) {
        unsigned long long we = build_win(Wp[c], x);
        int de = win_dist(we);
        if (de >= DINF) de = full_scan(&Wp[c][1], x, false);
        float w_eq = (de >= DINF) ? BIGF : ((float)de * (float)de);
        g_w[base + (unsigned)c * NPIX] = (c == t) ? w_own : w_eq;
    }
}

// ---------------------------------------------------------------------------
// Fused col pass: per class ONE ring loop serves both polarities (shared
// loads, decode via fmaxf). Early exit when q >= max(bp,bn); updates on a
// settled polarity are no-ops (candidate = v + q >= q >= best). Exact.
__global__ void __launch_bounds__(256) k_loss(const float* __restrict__ logits) {
    int pid = blockIdx.x * 256 + threadIdx.x;     // 0 .. BB*NPIX-1 (exact)
    int b = pid / NPIX;
    int r = pid - b * NPIX;
    int h = r / WW;

    float l0 = logits[(b * CC + 0) * NPIX + r];
    float l1 = logits[(b * CC + 1) * NPIX + r];
    float l2 = logits[(b * CC + 2) * NPIX + r];
    float l3 = logits[(b * CC + 3) * NPIX + r];
    float m = fmaxf(fmaxf(l0, l1), fmaxf(l2, l3));
    float e0 = __expf(l0 - m), e1 = __expf(l1 - m);
    float e2 = __expf(l2 - m), e3 = __expf(l3 - m);
    float inv = 1.0f / (e0 + e1 + e2 + e3);
    float pr[4] = { e0 * inv, e1 * inv, e2 * inv, e3 * inv };

    float acc = 0.0f;
#pragma unroll 1
    for (int c = 0; c < CC; ++c) {
        const float* pw = g_w + (unsigned)(b * CC + c) * NPIX;
        float w0 = __ldg(pw + r);
        float bp = fmaxf(w0, 0.0f);    // pos^2 running min
        float bn = fmaxf(-w0, 0.0f);   // neg^2 running min
        float q = 1.0f, stp = 3.0f;    // q = dh^2
        int offm = r - WW, offp = r + WW;
        int hm = h - 1, hp = h + 1;
#pragma unroll 1
        for (int dh = 1; dh < HH; ++dh) {
            if (q >= fmaxf(bp, bn)) break;
            if (hm >= 0) {
                float v = __ldg(pw + offm);
                bp = fminf(bp, fmaxf(v, 0.0f) + q);
                bn = fminf(bn, fmaxf(-v, 0.0f) + q);
            }
            if (hp < HH) {
                float v = __ldg(pw + offp);
                bp = fminf(bp, fmaxf(v, 0.0f) + q);
                bn = fminf(bn, fmaxf(-v, 0.0f) + q);
            }
            q += stp; stp += 2.0f;
            offm -= WW; offp += WW; --hm; ++hp;
        }
        // Empty/full detection from values: finite dist^2 <= 2*383^2 ~ 2.9e5
        // << 1e7; empty-mask surface stays exactly 1e8.
        float phi;
        if (bp >= 1e7f)       phi =  sqrtf(bp);
        else if (bn >= 1e7f)  phi = -sqrtf(bn);
        else                  phi =  sqrtf(bp) - sqrtf(bn) + 1.0f;
        acc += pr[c] * phi;
    }

    // block reduction (fixed shape -> deterministic)
    int lane = threadIdx.x & 31, wid = threadIdx.x >> 5;
#pragma unroll
    for (int o = 16; o; o >>= 1) acc += __shfl_down_sync(0xFFFFFFFFu, acc, o);
    __shared__ float sm[8];
    if (lane == 0) sm[wid] = acc;
    __syncthreads();
    if (threadIdx.x < 8) {
        float v = sm[threadIdx.x];
#pragma unroll
        for (int o = 4; o; o >>= 1) v += __shfl_down_sync(0x000000FFu, v, o);
        if (threadIdx.x == 0) g_part[blockIdx.x] = v;
    }
}

// ---------------------------------------------------------------------------
// Final reduce: 18 independent loads per thread (MLP), then add tree.
__global__ void __launch_bounds__(256) k_final(float* __restrict__ out) {
    int t = threadIdx.x;
    float a[18];
#pragma unroll
    for (int i = 0; i < 18; ++i) a[i] = g_part[t + i * 256];
    float s = 0.0f;
#pragma unroll
    for (int i = 0; i < 18; ++i) s += a[i];

    int lane = t & 31, wid = t >> 5;
#pragma unroll
    for (int o = 16; o; o >>= 1) s += __shfl_down_sync(0xFFFFFFFFu, s, o);
    __shared__ float sm[8];
    if (lane == 0) sm[wid] = s;
    __syncthreads();
    if (t < 8) {
        float v = sm[t];
#pragma unroll
        for (int o = 4; o; o >>= 1) v += __shfl_down_sync(0x000000FFu, v, o);
        if (t == 0)
            out[0] = v * (1.0f / ((float)BB * CC * NPIX));
    }
}

// ---------------------------------------------------------------------------
extern "C" void kernel_launch(void* const* d_in, const int* in_sizes, int n_in,
                              void* d_out, int out_size) {
    const float* logits  = (const float*)d_in[0];
    const int*   targets = (const int*)d_in[1];
    float* out = (float*)d_out;

    k_rowpass<<<BB * HH, 384>>>(targets);
    k_loss<<<NBLK3, 256>>>(logits);
    k_final<<<1, 256>>>(out);
}